// round 1
// baseline (speedup 1.0000x reference)
#include <cuda_runtime.h>

#define NTOK 8192
#define DIM  2048
#define NEXP 8

#define BM 128
#define BN 128
#define BK 16

// Routing scratch (device globals: no allocations allowed in kernel_launch)
__device__ int   g_count[NEXP];
__device__ int   g_tok[NEXP * NTOK];
__device__ float g_wt[NEXP * NTOK];

// ---------------------------------------------------------------------------
// Kernel 0: zero output buffer (poisoned by harness) + expert counters
// ---------------------------------------------------------------------------
__global__ void zero_out_kernel(float4* __restrict__ out) {
    int i = blockIdx.x * blockDim.x + threadIdx.x;
    out[i] = make_float4(0.f, 0.f, 0.f, 0.f);
    if (blockIdx.x == 0 && threadIdx.x < NEXP) g_count[threadIdx.x] = 0;
}

// ---------------------------------------------------------------------------
// Kernel 1: gating — one warp per token.
// logits = x @ Wg^T + bg ; softmax; top-2 (first-index tie-break, matching
// jax.lax.top_k); scatter token into per-expert lists with gate weights.
// ---------------------------------------------------------------------------
__global__ void gate_kernel(const float* __restrict__ x,
                            const float* __restrict__ Wg,
                            const float* __restrict__ bg) {
    int tok  = (blockIdx.x * blockDim.x + threadIdx.x) >> 5;
    int lane = threadIdx.x & 31;
    if (tok >= NTOK) return;

    const float* xr = x + (size_t)tok * DIM;
    float acc[NEXP];
#pragma unroll
    for (int e = 0; e < NEXP; e++) acc[e] = 0.f;

    for (int i = lane; i < DIM; i += 32) {
        float xv = xr[i];
#pragma unroll
        for (int e = 0; e < NEXP; e++)
            acc[e] = fmaf(xv, Wg[e * DIM + i], acc[e]);
    }
#pragma unroll
    for (int off = 16; off; off >>= 1) {
#pragma unroll
        for (int e = 0; e < NEXP; e++)
            acc[e] += __shfl_xor_sync(0xffffffffu, acc[e], off);
    }

    if (lane == 0) {
        float m = -3.4e38f;
#pragma unroll
        for (int e = 0; e < NEXP; e++) { acc[e] += bg[e]; m = fmaxf(m, acc[e]); }
        float p[NEXP];
        float s = 0.f;
#pragma unroll
        for (int e = 0; e < NEXP; e++) { p[e] = expf(acc[e] - m); s += p[e]; }

        // top-2 on softmax probs (monotonic in logits); strict '>' keeps the
        // earliest index on ties, matching jax.lax.top_k.
        int i0 = 0;
#pragma unroll
        for (int e = 1; e < NEXP; e++) if (p[e] > p[i0]) i0 = e;
        int i1 = (i0 == 0) ? 1 : 0;
#pragma unroll
        for (int e = 0; e < NEXP; e++)
            if (e != i0 && p[e] > p[i1]) i1 = e;

        float inv = 1.f / s;
        int p0 = atomicAdd(&g_count[i0], 1);
        g_tok[i0 * NTOK + p0] = tok;
        g_wt [i0 * NTOK + p0] = p[i0] * inv;
        int p1 = atomicAdd(&g_count[i1], 1);
        g_tok[i1 * NTOK + p1] = tok;
        g_wt [i1 * NTOK + p1] = p[i1] * inv;
    }
}

// ---------------------------------------------------------------------------
// Kernel 2: grouped gathered SGEMM per expert.
// C[m,n] = relu( Xg[m,:] . W[e][n,:] + b[e][n] ) * wt[m]  -> atomicAdd to out.
// 128x128 tile, BK=16, 256 threads, 8x8 per-thread (2x2 quadrants of 4x4).
// ---------------------------------------------------------------------------
__global__ void __launch_bounds__(256, 2)
moe_gemm_kernel(const float* __restrict__ x,
                const float* __restrict__ W,
                const float* __restrict__ bias,
                float* __restrict__ out) {
    int e   = blockIdx.z;
    int cnt = g_count[e];
    int m0  = blockIdx.x * BM;
    if (m0 >= cnt) return;
    int n0  = blockIdx.y * BN;

    __shared__ float As[BK][BM + 4];   // row stride 132 words: 16B-aligned, bank-spread
    __shared__ float Bs[BK][BN + 4];
    __shared__ int   toks[BM];
    __shared__ float wts[BM];

    int tid = threadIdx.x;

    if (tid < BM) {
        int mi = m0 + tid;
        if (mi < cnt) {
            toks[tid] = g_tok[e * NTOK + mi];
            wts [tid] = g_wt [e * NTOK + mi];
        } else {
            toks[tid] = -1;
            wts [tid] = 0.f;
        }
    }
    __syncthreads();

    // Loader mapping: thread -> (row = tid>>2 and +64, k-quad = (tid&3)*4)
    int lrow = tid >> 2;          // 0..63
    int lk   = (tid & 3) * 4;     // 0,4,8,12

    int t0a = toks[lrow];      if (t0a < 0) t0a = toks[0];
    int t1a = toks[lrow + 64]; if (t1a < 0) t1a = toks[0];
    const float* arow0 = x + (size_t)t0a * DIM + lk;
    const float* arow1 = x + (size_t)t1a * DIM + lk;
    const float* brow0 = W + ((size_t)e * DIM + (n0 + lrow)) * DIM + lk;
    const float* brow1 = brow0 + (size_t)64 * DIM;

    int tx = tid & 15;            // 0..15 -> cols 4*tx .. and +64
    int ty = tid >> 4;            // 0..15 -> rows 4*ty .. and +64

    float acc[8][8];
#pragma unroll
    for (int i = 0; i < 8; i++)
#pragma unroll
        for (int j = 0; j < 8; j++) acc[i][j] = 0.f;

    for (int k0 = 0; k0 < DIM; k0 += BK) {
        float4 a0 = *(const float4*)(arow0 + k0);
        float4 a1 = *(const float4*)(arow1 + k0);
        float4 b0 = *(const float4*)(brow0 + k0);
        float4 b1 = *(const float4*)(brow1 + k0);

        As[lk + 0][lrow]      = a0.x; As[lk + 1][lrow]      = a0.y;
        As[lk + 2][lrow]      = a0.z; As[lk + 3][lrow]      = a0.w;
        As[lk + 0][lrow + 64] = a1.x; As[lk + 1][lrow + 64] = a1.y;
        As[lk + 2][lrow + 64] = a1.z; As[lk + 3][lrow + 64] = a1.w;
        Bs[lk + 0][lrow]      = b0.x; Bs[lk + 1][lrow]      = b0.y;
        Bs[lk + 2][lrow]      = b0.z; Bs[lk + 3][lrow]      = b0.w;
        Bs[lk + 0][lrow + 64] = b1.x; Bs[lk + 1][lrow + 64] = b1.y;
        Bs[lk + 2][lrow + 64] = b1.z; Bs[lk + 3][lrow + 64] = b1.w;
        __syncthreads();

#pragma unroll
        for (int kk = 0; kk < BK; kk++) {
            float4 av0 = *(const float4*)&As[kk][ty * 4];
            float4 av1 = *(const float4*)&As[kk][ty * 4 + 64];
            float4 bv0 = *(const float4*)&Bs[kk][tx * 4];
            float4 bv1 = *(const float4*)&Bs[kk][tx * 4 + 64];
            float a[8] = {av0.x, av0.y, av0.z, av0.w, av1.x, av1.y, av1.z, av1.w};
            float b[8] = {bv0.x, bv0.y, bv0.z, bv0.w, bv1.x, bv1.y, bv1.z, bv1.w};
#pragma unroll
            for (int i = 0; i < 8; i++)
#pragma unroll
                for (int j = 0; j < 8; j++)
                    acc[i][j] = fmaf(a[i], b[j], acc[i][j]);
        }
        __syncthreads();
    }

    // Epilogue: bias + ReLU + gate-weight, scatter-add into out rows.
    float bset[8];
#pragma unroll
    for (int j = 0; j < 8; j++) {
        int n = n0 + tx * 4 + (j & 3) + (j >> 2) * 64;
        bset[j] = bias[e * DIM + n];
    }
#pragma unroll
    for (int i = 0; i < 8; i++) {
        int mrow = ty * 4 + (i & 3) + (i >> 2) * 64;
        int tok  = toks[mrow];
        if (tok < 0) continue;
        float wgt = wts[mrow];
        float* orow = out + (size_t)tok * DIM;
#pragma unroll
        for (int j = 0; j < 8; j++) {
            int n = n0 + tx * 4 + (j & 3) + (j >> 2) * 64;
            float v = acc[i][j] + bset[j];
            v = fmaxf(v, 0.f) * wgt;
            atomicAdd(orow + n, v);
        }
    }
}

// ---------------------------------------------------------------------------
extern "C" void kernel_launch(void* const* d_in, const int* in_sizes, int n_in,
                              void* d_out, int out_size) {
    const float* x  = (const float*)d_in[0];   // [B, D]
    const float* W  = (const float*)d_in[1];   // [E, D, D]
    const float* b  = (const float*)d_in[2];   // [E, D]
    const float* Wg = (const float*)d_in[3];   // [E, D]
    const float* bg = (const float*)d_in[4];   // [E]
    float* out = (float*)d_out;                // [B, D] fp32

    (void)in_sizes; (void)n_in; (void)out_size;

    // 1) zero out + counters
    int nvec4 = NTOK * DIM / 4;                 // 4,194,304
    zero_out_kernel<<<nvec4 / 256, 256>>>((float4*)out);

    // 2) gating / routing: one warp per token
    gate_kernel<<<(NTOK * 32) / 256, 256>>>(x, Wg, bg);

    // 3) grouped sparse GEMM over (row-tile, col-tile, expert)
    dim3 grid(NTOK / BM, DIM / BN, NEXP);
    moe_gemm_kernel<<<grid, 256>>>(x, W, b, out);
}

// round 3
// speedup vs baseline: 1.8289x; 1.8289x over previous
#include <cuda_runtime.h>
#include <cstdint>

#define NTOK 8192
#define DIM  2048
#define NEXP 8
#define TOPK 2

#define BM 128
#define BN 128
#define BK 32
#define STAGES 3
#define KITERS (DIM / BK)              // 64

#define PACK_ROWS (NTOK * TOPK + NEXP * BM)   // 17408
#define MAXTILES 160
#define GRID_ROWTILES 136

// smem geometry (words): tile row stride 36 (pad 4) -> conflict-free frag loads
#define AW 4608                         // 128*36 words per stage
#define BOFF (STAGES * AW)              // B region word offset
#define SMEM_TOTAL (2 * STAGES * AW * 4)  // 110592 bytes

// ---------------- device globals ----------------
__device__ int   g_count[NEXP];
__device__ int   g_tok[NEXP * NTOK];
__device__ float g_wt [NEXP * NTOK];
__device__ int4  g_route[NTOK];
__device__ int   g_off[NEXP + 1];
__device__ int   g_ntiles;
__device__ int   g_tile_e[MAXTILES];
__device__ int   g_tile_r[MAXTILES];
__device__ int   g_ptok[PACK_ROWS];
__device__ float g_pwt [PACK_ROWS];
__device__ float g_xpack[(size_t)PACK_ROWS * DIM];
__device__ float g_wtf [(size_t)NEXP * DIM * DIM];
__device__ float g_opack[(size_t)PACK_ROWS * DIM];

// ---------------- helpers ----------------
__device__ __forceinline__ float tf32r(float x) {
    uint32_t u;
    asm("cvt.rna.tf32.f32 %0, %1;" : "=r"(u) : "f"(x));
    return __uint_as_float(u);
}
__device__ __forceinline__ uint32_t smem_u32(const void* p) {
    uint32_t a;
    asm("{ .reg .u64 t; cvta.to.shared.u64 t, %1; cvt.u32.u64 %0, t; }" : "=r"(a) : "l"(p));
    return a;
}
#define CP16(dst, src) \
    asm volatile("cp.async.cg.shared.global [%0], [%1], 16;" :: "r"(dst), "l"(src) : "memory")
#define CP_COMMIT() asm volatile("cp.async.commit_group;" ::: "memory")
#define CP_WAIT1()  asm volatile("cp.async.wait_group 1;" ::: "memory")
#define CP_WAIT0()  asm volatile("cp.async.wait_group 0;" ::: "memory")

__device__ __forceinline__ void mma_tf32(float* d, const uint32_t* a, const uint32_t* b) {
    asm volatile(
        "mma.sync.aligned.m16n8k8.row.col.f32.tf32.tf32.f32 "
        "{%0,%1,%2,%3}, {%4,%5,%6,%7}, {%8,%9}, {%0,%1,%2,%3};"
        : "+f"(d[0]), "+f"(d[1]), "+f"(d[2]), "+f"(d[3])
        : "r"(a[0]), "r"(a[1]), "r"(a[2]), "r"(a[3]), "r"(b[0]), "r"(b[1]));
}

// ---------------- kernel 0: init ----------------
__global__ void init_kernel() {
    if (threadIdx.x < NEXP) g_count[threadIdx.x] = 0;
}

// ---------------- kernel 1: gating ----------------
__global__ void gate_kernel(const float* __restrict__ x,
                            const float* __restrict__ Wg,
                            const float* __restrict__ bg) {
    int tok  = (blockIdx.x * blockDim.x + threadIdx.x) >> 5;
    int lane = threadIdx.x & 31;
    if (tok >= NTOK) return;

    const float* xr = x + (size_t)tok * DIM;
    float acc[NEXP];
#pragma unroll
    for (int e = 0; e < NEXP; e++) acc[e] = 0.f;
    for (int i = lane; i < DIM; i += 32) {
        float xv = xr[i];
#pragma unroll
        for (int e = 0; e < NEXP; e++)
            acc[e] = fmaf(xv, Wg[e * DIM + i], acc[e]);
    }
#pragma unroll
    for (int off = 16; off; off >>= 1)
#pragma unroll
        for (int e = 0; e < NEXP; e++)
            acc[e] += __shfl_xor_sync(0xffffffffu, acc[e], off);

    if (lane == 0) {
        float m = -3.4e38f;
#pragma unroll
        for (int e = 0; e < NEXP; e++) { acc[e] += bg[e]; m = fmaxf(m, acc[e]); }
        float p[NEXP], s = 0.f;
#pragma unroll
        for (int e = 0; e < NEXP; e++) { p[e] = expf(acc[e] - m); s += p[e]; }
        int i0 = 0;
#pragma unroll
        for (int e = 1; e < NEXP; e++) if (p[e] > p[i0]) i0 = e;
        int i1 = (i0 == 0) ? 1 : 0;
#pragma unroll
        for (int e = 0; e < NEXP; e++)
            if (e != i0 && p[e] > p[i1]) i1 = e;

        float inv = 1.f / s;
        int p0 = atomicAdd(&g_count[i0], 1);
        g_tok[i0 * NTOK + p0] = tok;
        g_wt [i0 * NTOK + p0] = p[i0] * inv;
        int p1 = atomicAdd(&g_count[i1], 1);
        g_tok[i1 * NTOK + p1] = tok;
        g_wt [i1 * NTOK + p1] = p[i1] * inv;
        g_route[tok] = make_int4(i0, p0, i1, p1);
    }
}

// ---------------- kernel 2: schedule ----------------
__global__ void sched_kernel() {
    if (threadIdx.x == 0) {
        int off = 0, nt = 0;
        for (int e = 0; e < NEXP; e++) {
            g_off[e] = off;
            int c = g_count[e];
            int t = (c + BM - 1) / BM;
            for (int i = 0; i < t; i++) { g_tile_e[nt] = e; g_tile_r[nt] = i * BM; nt++; }
            off += t * BM;
        }
        g_off[NEXP] = off;
        g_ntiles = nt;
    }
}

// ---------------- kernel 3: pack ----------------
__global__ void pack_kernel(const float* __restrict__ x) {
    int r = blockIdx.x;
    int e = -1;
#pragma unroll
    for (int i = 0; i < NEXP; i++)
        if (r >= g_off[i] && r < g_off[i + 1]) e = i;
    if (e < 0) return;

    int local = r - g_off[e];
    int cnt   = g_count[e];
    float4* dst = (float4*)(g_xpack + (size_t)r * DIM);
    int tid = threadIdx.x;

    if (local < cnt) {
        int tok = g_tok[e * NTOK + local];
        if (tid == 0) { g_ptok[r] = tok; g_pwt[r] = g_wt[e * NTOK + local]; }
        const float4* src = (const float4*)(x + (size_t)tok * DIM);
        for (int i = tid; i < DIM / 4; i += 256) {
            float4 v = src[i];
            v.x = tf32r(v.x); v.y = tf32r(v.y); v.z = tf32r(v.z); v.w = tf32r(v.w);
            dst[i] = v;
        }
    } else {
        if (tid == 0) g_ptok[r] = -1;
        float4 z = make_float4(0.f, 0.f, 0.f, 0.f);
        for (int i = tid; i < DIM / 4; i += 256) dst[i] = z;
    }
}

// ---------------- kernel 4: W -> tf32 ----------------
__global__ void wround_kernel(const float4* __restrict__ W) {
    size_t i = (size_t)blockIdx.x * blockDim.x + threadIdx.x;
    float4 v = W[i];
    v.x = tf32r(v.x); v.y = tf32r(v.y); v.z = tf32r(v.z); v.w = tf32r(v.w);
    ((float4*)g_wtf)[i] = v;
}

// ---------------- kernel 5: TF32 mma.sync grouped GEMM ----------------
// 128x128x2048, 256 thr, warps 4(M)x2(N), warp tile 32x64, m16n8k8.
__global__ void __launch_bounds__(256, 1)
moe_mma_gemm(const float* __restrict__ bias) {
    int bx = blockIdx.x;
    if (bx >= g_ntiles) return;
    int e   = g_tile_e[bx];
    int m_g = g_off[e] + g_tile_r[bx];
    int n0  = blockIdx.y * BN;

    extern __shared__ char smem[];
    uint32_t sbase = smem_u32(smem);
    uint32_t* smw  = (uint32_t*)smem;

    int tid    = threadIdx.x;
    int lane   = tid & 31;
    int wid    = tid >> 5;
    int warp_m = wid & 3;          // 0..3 -> 32-row slab
    int warp_n = wid >> 2;         // 0..1 -> 64-col slab
    int fr     = lane >> 2;        // fragment row/col group
    int fc     = lane & 3;

    // per-thread global load coords
    int lrow = tid >> 1;           // 0..127
    int lq   = (tid & 1) * 16;     // float offset within BK
    const float* gA = g_xpack + (size_t)(m_g + lrow) * DIM + lq;
    const float* gB = g_wtf + ((size_t)e * DIM + n0 + lrow) * DIM + lq;
    uint32_t dA = sbase + (lrow * 36 + lq) * 4;
    uint32_t dB = sbase + (BOFF + lrow * 36 + lq) * 4;

    float acc[2][8][4];
#pragma unroll
    for (int i = 0; i < 2; i++)
#pragma unroll
        for (int j = 0; j < 8; j++)
#pragma unroll
            for (int k = 0; k < 4; k++) acc[i][j][k] = 0.f;

    // prologue: stages 0..STAGES-2
#pragma unroll
    for (int s = 0; s < STAGES - 1; s++) {
        const float* pa = gA + s * BK;
        const float* pb = gB + s * BK;
        uint32_t da = dA + s * (AW * 4);
        uint32_t db = dB + s * (AW * 4);
#pragma unroll
        for (int i = 0; i < 4; i++) {
            CP16(da + i * 16, pa + i * 4);
            CP16(db + i * 16, pb + i * 4);
        }
        CP_COMMIT();
    }

#pragma unroll 1
    for (int kt = 0; kt < KITERS; kt++) {
        if (kt < KITERS - 1) { CP_WAIT1(); } else { CP_WAIT0(); }
        __syncthreads();

        int kp = kt + STAGES - 1;
        if (kp < KITERS) {
            int s = kp % STAGES;
            const float* pa = gA + kp * BK;
            const float* pb = gB + kp * BK;
            uint32_t da = dA + s * (AW * 4);
            uint32_t db = dB + s * (AW * 4);
#pragma unroll
            for (int i = 0; i < 4; i++) {
                CP16(da + i * 16, pa + i * 4);
                CP16(db + i * 16, pb + i * 4);
            }
            CP_COMMIT();
        }

        const uint32_t* As = smw + (kt % STAGES) * AW;
        const uint32_t* Bs = smw + BOFF + (kt % STAGES) * AW;

#pragma unroll
        for (int kk = 0; kk < BK / 8; kk++) {
            int kb = kk * 8 + fc;
            uint32_t a[2][4], bf[8][2];
#pragma unroll
            for (int tm = 0; tm < 2; tm++) {
                int base = (warp_m * 32 + tm * 16 + fr) * 36 + kb;
                a[tm][0] = As[base];
                a[tm][1] = As[base + 8 * 36];
                a[tm][2] = As[base + 4];
                a[tm][3] = As[base + 8 * 36 + 4];
            }
#pragma unroll
            for (int tn = 0; tn < 8; tn++) {
                int nb = (warp_n * 64 + tn * 8 + fr) * 36 + kb;
                bf[tn][0] = Bs[nb];
                bf[tn][1] = Bs[nb + 4];
            }
#pragma unroll
            for (int tm = 0; tm < 2; tm++)
#pragma unroll
                for (int tn = 0; tn < 8; tn++)
                    mma_tf32(acc[tm][tn], a[tm], bf[tn]);
        }
        __syncthreads();
    }

    // epilogue: bias + relu + gate weight -> packed rows (no atomics)
    int c2 = 2 * fc;
    float2 bv[8];
#pragma unroll
    for (int tn = 0; tn < 8; tn++) {
        const float* bp = bias + (size_t)e * DIM + n0 + warp_n * 64 + tn * 8 + c2;
        bv[tn] = make_float2(__ldg(bp), __ldg(bp + 1));
    }
#pragma unroll
    for (int tm = 0; tm < 2; tm++) {
#pragma unroll
        for (int half = 0; half < 2; half++) {
            int row  = warp_m * 32 + tm * 16 + half * 8 + fr;
            int prow = m_g + row;
            int tok  = g_ptok[prow];
            if (tok < 0) continue;
            float wgt = g_pwt[prow];
            float* orow = g_opack + (size_t)prow * DIM + n0 + warp_n * 64;
#pragma unroll
            for (int tn = 0; tn < 8; tn++) {
                float v0 = fmaxf(acc[tm][tn][half * 2 + 0] + bv[tn].x, 0.f) * wgt;
                float v1 = fmaxf(acc[tm][tn][half * 2 + 1] + bv[tn].y, 0.f) * wgt;
                *(float2*)(orow + tn * 8 + c2) = make_float2(v0, v1);
            }
        }
    }
}

// ---------------- kernel 6: combine ----------------
__global__ void combine_kernel(float* __restrict__ out) {
    int t = blockIdx.x;
    int4 rt = g_route[t];
    const float4* a = (const float4*)(g_opack + (size_t)(g_off[rt.x] + rt.y) * DIM);
    const float4* b = (const float4*)(g_opack + (size_t)(g_off[rt.z] + rt.w) * DIM);
    float4* o = (float4*)(out + (size_t)t * DIM);
    for (int i = threadIdx.x; i < DIM / 4; i += 256) {
        float4 va = a[i], vb = b[i];
        o[i] = make_float4(va.x + vb.x, va.y + vb.y, va.z + vb.z, va.w + vb.w);
    }
}

// ---------------- launch ----------------
extern "C" void kernel_launch(void* const* d_in, const int* in_sizes, int n_in,
                              void* d_out, int out_size) {
    const float* x  = (const float*)d_in[0];
    const float* W  = (const float*)d_in[1];
    const float* b  = (const float*)d_in[2];
    const float* Wg = (const float*)d_in[3];
    const float* bg = (const float*)d_in[4];
    float* out = (float*)d_out;
    (void)in_sizes; (void)n_in; (void)out_size;

    cudaFuncSetAttribute(moe_mma_gemm, cudaFuncAttributeMaxDynamicSharedMemorySize, SMEM_TOTAL);

    init_kernel<<<1, 32>>>();
    gate_kernel<<<(NTOK * 32) / 256, 256>>>(x, Wg, bg);
    sched_kernel<<<1, 32>>>();
    pack_kernel<<<PACK_ROWS, 256>>>(x);
    wround_kernel<<<(NEXP * DIM * DIM / 4) / 256, 256>>>((const float4*)W);
    moe_mma_gemm<<<dim3(GRID_ROWTILES, DIM / BN), 256, SMEM_TOTAL>>>(b);
    combine_kernel<<<NTOK, 256>>>(out);
}

// round 4
// speedup vs baseline: 4.6517x; 2.5434x over previous
#include <cuda_runtime.h>
#include <cuda_fp16.h>
#include <cstdint>

#define NTOK 8192
#define DIM  2048
#define NEXP 8
#define TOPK 2

#define BM 128
#define BN 128
#define BK 64                          // halves per k-iter
#define STAGES 3
#define KITERS (DIM / BK)              // 32

#define PACK_ROWS (NTOK * TOPK + NEXP * BM)   // 17408
#define MAXTILES 160
#define GRID_ROWTILES 136

#define STAGE_BYTES (BM * BK * 2)      // 16384
#define SMEM_TOTAL  (2 * STAGES * STAGE_BYTES)  // 98304

// ---------------- device globals ----------------
__device__ int    g_count[NEXP];
__device__ int    g_tok[NEXP * NTOK];
__device__ float  g_wt [NEXP * NTOK];
__device__ int4   g_route[NTOK];
__device__ int    g_off[NEXP + 1];
__device__ int    g_ntiles;
__device__ int    g_tile_e[MAXTILES];
__device__ int    g_tile_r[MAXTILES];
__device__ int    g_ptok[PACK_ROWS];
__device__ float  g_pwt [PACK_ROWS];
__device__ __half g_xh[(size_t)PACK_ROWS * DIM];     // gathered fp16 A
__device__ __half g_wh[(size_t)NEXP * DIM * DIM];    // fp16 W
__device__ float  g_opack[(size_t)PACK_ROWS * DIM];  // per-(expert,row) outputs

// ---------------- helpers ----------------
__device__ __forceinline__ uint32_t smem_u32(const void* p) {
    uint32_t a;
    asm("{ .reg .u64 t; cvta.to.shared.u64 t, %1; cvt.u32.u64 %0, t; }" : "=r"(a) : "l"(p));
    return a;
}
#define CP16(dst, src) \
    asm volatile("cp.async.cg.shared.global [%0], [%1], 16;" :: "r"(dst), "l"(src) : "memory")
#define CP_COMMIT() asm volatile("cp.async.commit_group;" ::: "memory")
#define CP_WAIT1()  asm volatile("cp.async.wait_group 1;" ::: "memory")
#define CP_WAIT0()  asm volatile("cp.async.wait_group 0;" ::: "memory")

#define LDSM4(r0, r1, r2, r3, addr) \
    asm volatile("ldmatrix.sync.aligned.m8n8.x4.shared.b16 {%0,%1,%2,%3}, [%4];" \
        : "=r"(r0), "=r"(r1), "=r"(r2), "=r"(r3) : "r"(addr))

__device__ __forceinline__ void mma_f16(float* d, const uint32_t* a, const uint32_t* b) {
    asm volatile(
        "mma.sync.aligned.m16n8k16.row.col.f32.f16.f16.f32 "
        "{%0,%1,%2,%3}, {%4,%5,%6,%7}, {%8,%9}, {%0,%1,%2,%3};"
        : "+f"(d[0]), "+f"(d[1]), "+f"(d[2]), "+f"(d[3])
        : "r"(a[0]), "r"(a[1]), "r"(a[2]), "r"(a[3]), "r"(b[0]), "r"(b[1]));
}

// ---------------- kernel 0: init ----------------
__global__ void init_kernel() {
    if (threadIdx.x < NEXP) g_count[threadIdx.x] = 0;
}

// ---------------- kernel 1: gating (fp32, routing identical to reference) ----
__global__ void gate_kernel(const float* __restrict__ x,
                            const float* __restrict__ Wg,
                            const float* __restrict__ bg) {
    int tok  = (blockIdx.x * blockDim.x + threadIdx.x) >> 5;
    int lane = threadIdx.x & 31;
    if (tok >= NTOK) return;

    const float* xr = x + (size_t)tok * DIM;
    float acc[NEXP];
#pragma unroll
    for (int e = 0; e < NEXP; e++) acc[e] = 0.f;
    for (int i = lane; i < DIM; i += 32) {
        float xv = xr[i];
#pragma unroll
        for (int e = 0; e < NEXP; e++)
            acc[e] = fmaf(xv, Wg[e * DIM + i], acc[e]);
    }
#pragma unroll
    for (int off = 16; off; off >>= 1)
#pragma unroll
        for (int e = 0; e < NEXP; e++)
            acc[e] += __shfl_xor_sync(0xffffffffu, acc[e], off);

    if (lane == 0) {
        float m = -3.4e38f;
#pragma unroll
        for (int e = 0; e < NEXP; e++) { acc[e] += bg[e]; m = fmaxf(m, acc[e]); }
        float p[NEXP], s = 0.f;
#pragma unroll
        for (int e = 0; e < NEXP; e++) { p[e] = expf(acc[e] - m); s += p[e]; }
        int i0 = 0;
#pragma unroll
        for (int e = 1; e < NEXP; e++) if (p[e] > p[i0]) i0 = e;
        int i1 = (i0 == 0) ? 1 : 0;
#pragma unroll
        for (int e = 0; e < NEXP; e++)
            if (e != i0 && p[e] > p[i1]) i1 = e;

        float inv = 1.f / s;
        int p0 = atomicAdd(&g_count[i0], 1);
        g_tok[i0 * NTOK + p0] = tok;
        g_wt [i0 * NTOK + p0] = p[i0] * inv;
        int p1 = atomicAdd(&g_count[i1], 1);
        g_tok[i1 * NTOK + p1] = tok;
        g_wt [i1 * NTOK + p1] = p[i1] * inv;
        g_route[tok] = make_int4(i0, p0, i1, p1);
    }
}

// ---------------- kernel 2: schedule ----------------
__global__ void sched_kernel() {
    if (threadIdx.x == 0) {
        int off = 0, nt = 0;
        for (int e = 0; e < NEXP; e++) {
            g_off[e] = off;
            int c = g_count[e];
            int t = (c + BM - 1) / BM;
            for (int i = 0; i < t; i++) { g_tile_e[nt] = e; g_tile_r[nt] = i * BM; nt++; }
            off += t * BM;
        }
        g_off[NEXP] = off;
        g_ntiles = nt;
    }
}

// ---------------- kernel 3: pack (gather + fp16 convert) ----------------
__global__ void pack_kernel(const float* __restrict__ x) {
    int r = blockIdx.x;
    int e = -1;
#pragma unroll
    for (int i = 0; i < NEXP; i++)
        if (r >= g_off[i] && r < g_off[i + 1]) e = i;
    if (e < 0) return;

    int local = r - g_off[e];
    int cnt   = g_count[e];
    __half2* dst = (__half2*)(g_xh + (size_t)r * DIM);
    int tid = threadIdx.x;

    if (local < cnt) {
        int tok = g_tok[e * NTOK + local];
        if (tid == 0) { g_ptok[r] = tok; g_pwt[r] = g_wt[e * NTOK + local]; }
        const float4* src = (const float4*)(x + (size_t)tok * DIM);
        for (int i = tid; i < DIM / 4; i += 256) {
            float4 v = src[i];
            dst[2 * i]     = __floats2half2_rn(v.x, v.y);
            dst[2 * i + 1] = __floats2half2_rn(v.z, v.w);
        }
    } else {
        if (tid == 0) g_ptok[r] = -1;
        __half2 z = __floats2half2_rn(0.f, 0.f);
        for (int i = tid; i < DIM / 4; i += 256) { dst[2 * i] = z; dst[2 * i + 1] = z; }
    }
}

// ---------------- kernel 4: W -> fp16 ----------------
__global__ void whalf_kernel(const float4* __restrict__ W) {
    size_t i = (size_t)blockIdx.x * blockDim.x + threadIdx.x;
    float4 v = W[i];
    __half2* dst = (__half2*)g_wh;
    dst[2 * i]     = __floats2half2_rn(v.x, v.y);
    dst[2 * i + 1] = __floats2half2_rn(v.z, v.w);
}

// ---------------- kernel 5: FP16 mma.sync grouped GEMM ----------------
// 128x128x2048 fp16->fp32, 256 thr, warps 4(M)x2(N), warp tile 32x64,
// m16n8k16, ldmatrix fragment loads, 3-stage cp.async pipeline.
__global__ void __launch_bounds__(256, 2)
moe_mma_gemm(const float* __restrict__ bias) {
    int bx = blockIdx.x;
    if (bx >= g_ntiles) return;
    int e   = g_tile_e[bx];
    int m_g = g_off[e] + g_tile_r[bx];
    int n0  = blockIdx.y * BN;

    extern __shared__ char smem[];
    uint32_t sbase = smem_u32(smem);

    int tid    = threadIdx.x;
    int lane   = tid & 31;
    int wid    = tid >> 5;
    int warp_m = wid & 3;          // 32-row slab
    int warp_n = wid >> 2;         // 64-col slab
    int fr     = lane >> 2;
    int fc     = lane & 3;

    // global loads: 2 threads per row, 4x16B chunks each
    int lrow = tid >> 1;                  // 0..127
    int cgrp = (tid & 1) * 4;             // chunk group 0..3 / 4..7
    const __half* gA = g_xh + (size_t)(m_g + lrow) * DIM + cgrp * 8;
    const __half* gB = g_wh + ((size_t)e * DIM + n0 + lrow) * DIM + cgrp * 8;
    uint32_t rowOff = lrow * 128;
    int      rSw    = lrow & 7;

    // ldmatrix lane addressing precompute
    int mi  = lane >> 3;                  // matrix index 0..3
    int r8  = lane & 7;
    // A: mat i -> row_off (i&1)*8, k-half i>>1
    int aCh = mi >> 1;
    uint32_t aBase[2];
    int      aSw[2];
#pragma unroll
    for (int tm = 0; tm < 2; tm++) {
        int r = warp_m * 32 + tm * 16 + (mi & 1) * 8 + r8;
        aBase[tm] = r * 128;
        aSw[tm]   = r & 7;
    }
    // B: pair p covers n-tiles 2p,2p+1; mat j -> tile_off j>>1, k-half j&1
    int bCh = mi & 1;
    uint32_t bBase[4];
    int      bSw[4];
#pragma unroll
    for (int p = 0; p < 4; p++) {
        int r = warp_n * 64 + (2 * p + (mi >> 1)) * 8 + r8;
        bBase[p] = r * 128;
        bSw[p]   = r & 7;
    }

    float acc[2][8][4];
#pragma unroll
    for (int i = 0; i < 2; i++)
#pragma unroll
        for (int j = 0; j < 8; j++)
#pragma unroll
            for (int k = 0; k < 4; k++) acc[i][j][k] = 0.f;

    auto load_stage = [&](int s, int kt) {
        uint32_t da = sbase + s * STAGE_BYTES + rowOff;
        uint32_t db = sbase + (STAGES + s) * STAGE_BYTES + rowOff;
        const __half* pa = gA + kt * BK;
        const __half* pb = gB + kt * BK;
#pragma unroll
        for (int c = 0; c < 4; c++) {
            uint32_t pc = (uint32_t)((cgrp + c) ^ rSw) << 4;
            CP16(da + pc, pa + c * 8);
            CP16(db + pc, pb + c * 8);
        }
        CP_COMMIT();
    };

#pragma unroll
    for (int s = 0; s < STAGES - 1; s++) load_stage(s, s);

#pragma unroll 1
    for (int kt = 0; kt < KITERS; kt++) {
        if (kt < KITERS - 1) { CP_WAIT1(); } else { CP_WAIT0(); }
        __syncthreads();

        int kp = kt + STAGES - 1;
        if (kp < KITERS) load_stage(kp % STAGES, kp);

        uint32_t As = sbase + (kt % STAGES) * STAGE_BYTES;
        uint32_t Bs = sbase + (STAGES + (kt % STAGES)) * STAGE_BYTES;

#pragma unroll
        for (int kk = 0; kk < BK / 16; kk++) {
            uint32_t a[2][4], bf[16];
#pragma unroll
            for (int tm = 0; tm < 2; tm++) {
                uint32_t addr = As + aBase[tm] +
                                ((uint32_t)((kk * 2 + aCh) ^ aSw[tm]) << 4);
                LDSM4(a[tm][0], a[tm][1], a[tm][2], a[tm][3], addr);
            }
#pragma unroll
            for (int p = 0; p < 4; p++) {
                uint32_t addr = Bs + bBase[p] +
                                ((uint32_t)((kk * 2 + bCh) ^ bSw[p]) << 4);
                LDSM4(bf[4 * p], bf[4 * p + 1], bf[4 * p + 2], bf[4 * p + 3], addr);
            }
#pragma unroll
            for (int tm = 0; tm < 2; tm++)
#pragma unroll
                for (int tn = 0; tn < 8; tn++)
                    mma_f16(acc[tm][tn], a[tm], &bf[tn * 2]);
        }
        __syncthreads();
    }

    // epilogue: bias + relu + gate weight -> packed rows (no atomics)
    int c2 = 2 * fc;
    float2 bv[8];
#pragma unroll
    for (int tn = 0; tn < 8; tn++) {
        const float* bp = bias + (size_t)e * DIM + n0 + warp_n * 64 + tn * 8 + c2;
        bv[tn] = make_float2(__ldg(bp), __ldg(bp + 1));
    }
#pragma unroll
    for (int tm = 0; tm < 2; tm++) {
#pragma unroll
        for (int half = 0; half < 2; half++) {
            int row  = warp_m * 32 + tm * 16 + half * 8 + fr;
            int prow = m_g + row;
            int tok  = g_ptok[prow];
            if (tok < 0) continue;
            float wgt = g_pwt[prow];
            float* orow = g_opack + (size_t)prow * DIM + n0 + warp_n * 64;
#pragma unroll
            for (int tn = 0; tn < 8; tn++) {
                float v0 = fmaxf(acc[tm][tn][half * 2 + 0] + bv[tn].x, 0.f) * wgt;
                float v1 = fmaxf(acc[tm][tn][half * 2 + 1] + bv[tn].y, 0.f) * wgt;
                *(float2*)(orow + tn * 8 + c2) = make_float2(v0, v1);
            }
        }
    }
}

// ---------------- kernel 6: combine (atomic-free) ----------------
__global__ void combine_kernel(float* __restrict__ out) {
    int t = blockIdx.x;
    int4 rt = g_route[t];
    const float4* a = (const float4*)(g_opack + (size_t)(g_off[rt.x] + rt.y) * DIM);
    const float4* b = (const float4*)(g_opack + (size_t)(g_off[rt.z] + rt.w) * DIM);
    float4* o = (float4*)(out + (size_t)t * DIM);
    for (int i = threadIdx.x; i < DIM / 4; i += 256) {
        float4 va = a[i], vb = b[i];
        o[i] = make_float4(va.x + vb.x, va.y + vb.y, va.z + vb.z, va.w + vb.w);
    }
}

// ---------------- launch ----------------
extern "C" void kernel_launch(void* const* d_in, const int* in_sizes, int n_in,
                              void* d_out, int out_size) {
    const float* x  = (const float*)d_in[0];
    const float* W  = (const float*)d_in[1];
    const float* b  = (const float*)d_in[2];
    const float* Wg = (const float*)d_in[3];
    const float* bg = (const float*)d_in[4];
    float* out = (float*)d_out;
    (void)in_sizes; (void)n_in; (void)out_size;

    cudaFuncSetAttribute(moe_mma_gemm, cudaFuncAttributeMaxDynamicSharedMemorySize, SMEM_TOTAL);

    init_kernel<<<1, 32>>>();
    gate_kernel<<<(NTOK * 32) / 256, 256>>>(x, Wg, bg);
    sched_kernel<<<1, 32>>>();
    pack_kernel<<<PACK_ROWS, 256>>>(x);
    whalf_kernel<<<(NEXP * DIM * DIM / 4) / 256, 256>>>((const float4*)W);
    moe_mma_gemm<<<dim3(GRID_ROWTILES, DIM / BN), 256, SMEM_TOTAL>>>(b);
    combine_kernel<<<NTOK, 256>>>(out);
}

// round 5
// speedup vs baseline: 4.9982x; 1.0745x over previous
#include <cuda_runtime.h>
#include <cuda_fp16.h>
#include <cstdint>

#define NTOK 8192
#define DIM  2048
#define NEXP 8
#define TOPK 2

#define BM 128
#define BN 128
#define BK 64                          // halves per k-iter
#define STAGES 3
#define KITERS (DIM / BK)              // 32

#define MAXTILES 160
#define GRID_ROWTILES 136

#define STAGE_BYTES (BM * BK * 2)      // 16384
#define SMEM_TOTAL  (2 * STAGES * STAGE_BYTES)  // 98304

#define GATE_BLOCKS 1024               // 8 warps/block, 1 token/warp
#define CONV_BLOCKS 2048               // W-convert + out-zero slices
#define PREP_BLOCKS (GATE_BLOCKS + CONV_BLOCKS)

// ---------------- device globals ----------------
__device__ int    g_count[NEXP];
__device__ int    g_tok[NEXP * NTOK];
__device__ float  g_wt [NEXP * NTOK];
__device__ int    g_ntiles;
__device__ int    g_tile_e[MAXTILES];
__device__ int    g_tile_r[MAXTILES];
__device__ __half g_xh[(size_t)NEXP * NTOK * DIM];   // per-expert padded fp16 A
__device__ __half g_wh[(size_t)NEXP * DIM * DIM];    // fp16 W

// ---------------- helpers ----------------
__device__ __forceinline__ uint32_t smem_u32(const void* p) {
    uint32_t a;
    asm("{ .reg .u64 t; cvta.to.shared.u64 t, %1; cvt.u32.u64 %0, t; }" : "=r"(a) : "l"(p));
    return a;
}
#define CP16(dst, src) \
    asm volatile("cp.async.cg.shared.global [%0], [%1], 16;" :: "r"(dst), "l"(src) : "memory")
#define CP_COMMIT() asm volatile("cp.async.commit_group;" ::: "memory")
#define CP_WAIT1()  asm volatile("cp.async.wait_group 1;" ::: "memory")
#define CP_WAIT0()  asm volatile("cp.async.wait_group 0;" ::: "memory")

#define LDSM4(r0, r1, r2, r3, addr) \
    asm volatile("ldmatrix.sync.aligned.m8n8.x4.shared.b16 {%0,%1,%2,%3}, [%4];" \
        : "=r"(r0), "=r"(r1), "=r"(r2), "=r"(r3) : "r"(addr))

__device__ __forceinline__ void mma_f16(float* d, const uint32_t* a, const uint32_t* b) {
    asm volatile(
        "mma.sync.aligned.m16n8k16.row.col.f32.f16.f16.f32 "
        "{%0,%1,%2,%3}, {%4,%5,%6,%7}, {%8,%9}, {%0,%1,%2,%3};"
        : "+f"(d[0]), "+f"(d[1]), "+f"(d[2]), "+f"(d[3])
        : "r"(a[0]), "r"(a[1]), "r"(a[2]), "r"(a[3]), "r"(b[0]), "r"(b[1]));
}

// ---------------- kernel 0: init counters ----------------
__global__ void init_kernel() {
    if (threadIdx.x < NEXP) g_count[threadIdx.x] = 0;
}

// ---------------- kernel 1: fused prep ----------------
// blocks [0, GATE_BLOCKS): gating (1 warp/token) + fp16 row scatter into
//   per-expert padded slots (no prefix-sum needed).
// blocks [GATE_BLOCKS, PREP_BLOCKS): W fp32->fp16 slice + out-zero slice.
__global__ void __launch_bounds__(256)
prep_kernel(const float* __restrict__ x,
            const float4* __restrict__ W,
            const float* __restrict__ Wg,
            const float* __restrict__ bg,
            float4* __restrict__ out) {
    int bid = blockIdx.x;
    int tid = threadIdx.x;

    if (bid >= GATE_BLOCKS) {
        int cid = bid - GATE_BLOCKS;
        // W convert: 8,388,608 float4 over CONV_BLOCKS blocks
        {
            __half2* dst = (__half2*)g_wh;
            size_t base = (size_t)cid * 4096 + tid;
#pragma unroll 4
            for (int i = 0; i < 16; i++) {
                size_t idx = base + (size_t)i * 256;
                float4 v = W[idx];
                dst[2 * idx]     = __floats2half2_rn(v.x, v.y);
                dst[2 * idx + 1] = __floats2half2_rn(v.z, v.w);
            }
        }
        // zero out: 4,194,304 float4 over CONV_BLOCKS blocks
        {
            float4 z = make_float4(0.f, 0.f, 0.f, 0.f);
            size_t base = (size_t)cid * 2048 + tid;
#pragma unroll
            for (int i = 0; i < 8; i++)
                out[base + (size_t)i * 256] = z;
        }
        return;
    }

    // gating: token = bid*8 + warp
    int wid  = tid >> 5;
    int lane = tid & 31;
    int tok  = bid * 8 + wid;

    const float* xr = x + (size_t)tok * DIM;
    float acc[NEXP];
#pragma unroll
    for (int e = 0; e < NEXP; e++) acc[e] = 0.f;
    for (int i = lane; i < DIM; i += 32) {
        float xv = xr[i];
#pragma unroll
        for (int e = 0; e < NEXP; e++)
            acc[e] = fmaf(xv, Wg[e * DIM + i], acc[e]);
    }
#pragma unroll
    for (int off = 16; off; off >>= 1)
#pragma unroll
        for (int e = 0; e < NEXP; e++)
            acc[e] += __shfl_xor_sync(0xffffffffu, acc[e], off);

    int i0 = 0, i1 = 0, p0 = 0, p1 = 0;
    float w0 = 0.f, w1 = 0.f;
    if (lane == 0) {
        float m = -3.4e38f;
#pragma unroll
        for (int e = 0; e < NEXP; e++) { acc[e] += bg[e]; m = fmaxf(m, acc[e]); }
        float p[NEXP], s = 0.f;
#pragma unroll
        for (int e = 0; e < NEXP; e++) { p[e] = expf(acc[e] - m); s += p[e]; }
        i0 = 0;
#pragma unroll
        for (int e = 1; e < NEXP; e++) if (p[e] > p[i0]) i0 = e;
        i1 = (i0 == 0) ? 1 : 0;
#pragma unroll
        for (int e = 0; e < NEXP; e++)
            if (e != i0 && p[e] > p[i1]) i1 = e;

        float inv = 1.f / s;
        w0 = p[i0] * inv;
        w1 = p[i1] * inv;
        p0 = atomicAdd(&g_count[i0], 1);
        p1 = atomicAdd(&g_count[i1], 1);
        g_tok[i0 * NTOK + p0] = tok;  g_wt[i0 * NTOK + p0] = w0;
        g_tok[i1 * NTOK + p1] = tok;  g_wt[i1 * NTOK + p1] = w1;
    }
    i0 = __shfl_sync(0xffffffffu, i0, 0);
    i1 = __shfl_sync(0xffffffffu, i1, 0);
    p0 = __shfl_sync(0xffffffffu, p0, 0);
    p1 = __shfl_sync(0xffffffffu, p1, 0);

    // scatter fp16 row to both expert slots (x row re-read from L2)
    const float4* src = (const float4*)xr;
    __half2* d0 = (__half2*)(g_xh + ((size_t)i0 * NTOK + p0) * DIM);
    __half2* d1 = (__half2*)(g_xh + ((size_t)i1 * NTOK + p1) * DIM);
    for (int i = lane; i < DIM / 4; i += 32) {
        float4 v = src[i];
        __half2 h0 = __floats2half2_rn(v.x, v.y);
        __half2 h1 = __floats2half2_rn(v.z, v.w);
        d0[2 * i] = h0; d0[2 * i + 1] = h1;
        d1[2 * i] = h0; d1[2 * i + 1] = h1;
    }
}

// ---------------- kernel 2: schedule tiles ----------------
__global__ void sched_kernel() {
    if (threadIdx.x == 0) {
        int nt = 0;
        for (int e = 0; e < NEXP; e++) {
            int c = g_count[e];
            int t = (c + BM - 1) / BM;
            for (int i = 0; i < t; i++) { g_tile_e[nt] = e; g_tile_r[nt] = i * BM; nt++; }
        }
        g_ntiles = nt;
    }
}

// ---------------- kernel 3: FP16 mma.sync grouped GEMM, atomic epilogue ----
__global__ void __launch_bounds__(256, 2)
moe_mma_gemm(const float* __restrict__ bias, float* __restrict__ out) {
    int bx = blockIdx.x;
    if (bx >= g_ntiles) return;
    int e   = g_tile_e[bx];
    int r0  = g_tile_r[bx];
    int cnt = g_count[e];
    int n0  = blockIdx.y * BN;

    extern __shared__ char smem[];
    uint32_t sbase = smem_u32(smem);

    int tid    = threadIdx.x;
    int lane   = tid & 31;
    int wid    = tid >> 5;
    int warp_m = wid & 3;
    int warp_n = wid >> 2;
    int fr     = lane >> 2;
    int fc     = lane & 3;

    // global loads: 2 threads per row, 4x16B chunks each
    int lrow = tid >> 1;
    int cgrp = (tid & 1) * 4;
    const __half* gA = g_xh + ((size_t)e * NTOK + r0 + lrow) * DIM + cgrp * 8;
    const __half* gB = g_wh + ((size_t)e * DIM + n0 + lrow) * DIM + cgrp * 8;
    uint32_t rowOff = lrow * 128;
    int      rSw    = lrow & 7;

    int mi  = lane >> 3;
    int r8  = lane & 7;
    int aCh = mi >> 1;
    uint32_t aBase[2];
    int      aSw[2];
#pragma unroll
    for (int tm = 0; tm < 2; tm++) {
        int r = warp_m * 32 + tm * 16 + (mi & 1) * 8 + r8;
        aBase[tm] = r * 128;
        aSw[tm]   = r & 7;
    }
    int bCh = mi & 1;
    uint32_t bBase[4];
    int      bSw[4];
#pragma unroll
    for (int p = 0; p < 4; p++) {
        int r = warp_n * 64 + (2 * p + (mi >> 1)) * 8 + r8;
        bBase[p] = r * 128;
        bSw[p]   = r & 7;
    }

    float acc[2][8][4];
#pragma unroll
    for (int i = 0; i < 2; i++)
#pragma unroll
        for (int j = 0; j < 8; j++)
#pragma unroll
            for (int k = 0; k < 4; k++) acc[i][j][k] = 0.f;

    auto load_stage = [&](int s, int kt) {
        uint32_t da = sbase + s * STAGE_BYTES + rowOff;
        uint32_t db = sbase + (STAGES + s) * STAGE_BYTES + rowOff;
        const __half* pa = gA + kt * BK;
        const __half* pb = gB + kt * BK;
#pragma unroll
        for (int c = 0; c < 4; c++) {
            uint32_t pc = (uint32_t)((cgrp + c) ^ rSw) << 4;
            CP16(da + pc, pa + c * 8);
            CP16(db + pc, pb + c * 8);
        }
        CP_COMMIT();
    };

#pragma unroll
    for (int s = 0; s < STAGES - 1; s++) load_stage(s, s);

#pragma unroll 1
    for (int kt = 0; kt < KITERS; kt++) {
        if (kt < KITERS - 1) { CP_WAIT1(); } else { CP_WAIT0(); }
        __syncthreads();

        int kp = kt + STAGES - 1;
        if (kp < KITERS) load_stage(kp % STAGES, kp);

        uint32_t As = sbase + (kt % STAGES) * STAGE_BYTES;
        uint32_t Bs = sbase + (STAGES + (kt % STAGES)) * STAGE_BYTES;

#pragma unroll
        for (int kk = 0; kk < BK / 16; kk++) {
            uint32_t a[2][4], bf[16];
#pragma unroll
            for (int tm = 0; tm < 2; tm++) {
                uint32_t addr = As + aBase[tm] +
                                ((uint32_t)((kk * 2 + aCh) ^ aSw[tm]) << 4);
                LDSM4(a[tm][0], a[tm][1], a[tm][2], a[tm][3], addr);
            }
#pragma unroll
            for (int p = 0; p < 4; p++) {
                uint32_t addr = Bs + bBase[p] +
                                ((uint32_t)((kk * 2 + bCh) ^ bSw[p]) << 4);
                LDSM4(bf[4 * p], bf[4 * p + 1], bf[4 * p + 2], bf[4 * p + 3], addr);
            }
#pragma unroll
            for (int tm = 0; tm < 2; tm++)
#pragma unroll
                for (int tn = 0; tn < 8; tn++)
                    mma_f16(acc[tm][tn], a[tm], &bf[tn * 2]);
        }
        __syncthreads();
    }

    // epilogue: bias + relu + gate weight -> atomicAdd into out (2 adds/element
    // total across the grid; two-operand fp add is commutative -> deterministic)
    int c2 = 2 * fc;
    float2 bv[8];
#pragma unroll
    for (int tn = 0; tn < 8; tn++) {
        const float* bp = bias + (size_t)e * DIM + n0 + warp_n * 64 + tn * 8 + c2;
        bv[tn] = make_float2(__ldg(bp), __ldg(bp + 1));
    }
#pragma unroll
    for (int tm = 0; tm < 2; tm++) {
#pragma unroll
        for (int half = 0; half < 2; half++) {
            int row = warp_m * 32 + tm * 16 + half * 8 + fr;
            int idx = r0 + row;
            if (idx >= cnt) continue;
            int   tok = g_tok[e * NTOK + idx];
            float wgt = g_wt [e * NTOK + idx];
            float* orow = out + (size_t)tok * DIM + n0 + warp_n * 64;
#pragma unroll
            for (int tn = 0; tn < 8; tn++) {
                float v0 = fmaxf(acc[tm][tn][half * 2 + 0] + bv[tn].x, 0.f) * wgt;
                float v1 = fmaxf(acc[tm][tn][half * 2 + 1] + bv[tn].y, 0.f) * wgt;
                atomicAdd(orow + tn * 8 + c2,     v0);
                atomicAdd(orow + tn * 8 + c2 + 1, v1);
            }
        }
    }
}

// ---------------- launch ----------------
extern "C" void kernel_launch(void* const* d_in, const int* in_sizes, int n_in,
                              void* d_out, int out_size) {
    const float* x  = (const float*)d_in[0];
    const float* W  = (const float*)d_in[1];
    const float* b  = (const float*)d_in[2];
    const float* Wg = (const float*)d_in[3];
    const float* bg = (const float*)d_in[4];
    float* out = (float*)d_out;
    (void)in_sizes; (void)n_in; (void)out_size;

    cudaFuncSetAttribute(moe_mma_gemm, cudaFuncAttributeMaxDynamicSharedMemorySize, SMEM_TOTAL);

    init_kernel<<<1, 32>>>();
    prep_kernel<<<PREP_BLOCKS, 256>>>(x, (const float4*)W, Wg, bg, (float4*)out);
    sched_kernel<<<1, 32>>>();
    moe_mma_gemm<<<dim3(GRID_ROWTILES, DIM / BN), 256, SMEM_TOTAL>>>(b, out);
}